// round 14
// baseline (speedup 1.0000x reference)
#include <cuda_runtime.h>
#include <cuda_fp16.h>
#include <cstdint>
#include <math.h>

// Problem constants
#define BATCH 8
#define CIN   128
#define HW    3136        // 56*56
#define NPIX  25088       // 8*3136
#define MID   64
#define OUTC  256
#define KTOT  4096        // 64*64
#define EPS   1e-5f
#define PIXT  64          // pixels per CTA tile
#define NSPLIT 3          // K-split factor
#define STAGE_BYTES 32768 // one B chunk stage: 256 o x 64 d fp16, SW128

// Scratch: Wp in fp16, CHUNK-MAJOR PRE-SWIZZLED stage layout.
__device__ __align__(128) __half g_Whs[(size_t)OUTC * KTOT];
// K-split partial sums: [third][pix][o] fp32 (77 MB)
__device__ __align__(16) float g_part[(size_t)NSPLIT * NPIX * OUTC];

// ---------------------------------------------------------------------------
// Helpers (base-arch PTX only: cp.async.bulk / mbarrier / ldmatrix / mma.sync)
// ---------------------------------------------------------------------------
__device__ __forceinline__ uint32_t smem_u32(const void* p) {
    uint32_t a;
    asm("{ .reg .u64 t; cvta.to.shared.u64 t, %1; cvt.u32.u64 %0, t; }" : "=r"(a) : "l"(p));
    return a;
}
__device__ __forceinline__ uint32_t h2_u32(__half2 h) {
    union { __half2 h; uint32_t u; } cv;
    cv.h = h;
    return cv.u;
}
__device__ __forceinline__ __half2 u32_h2(uint32_t u) {
    union { __half2 h; uint32_t u; } cv;
    cv.u = u;
    return cv.h;
}
__device__ __forceinline__ void ldsm_x4(uint32_t& r0, uint32_t& r1, uint32_t& r2, uint32_t& r3,
                                        uint32_t addr) {
    asm volatile("ldmatrix.sync.aligned.m8n8.x4.shared.b16 {%0,%1,%2,%3}, [%4];"
                 : "=r"(r0), "=r"(r1), "=r"(r2), "=r"(r3) : "r"(addr));
}
__device__ __forceinline__ void mma16816(float* c, const uint32_t* a, uint32_t b0, uint32_t b1) {
    asm volatile(
        "mma.sync.aligned.m16n8k16.row.col.f32.f16.f16.f32 "
        "{%0,%1,%2,%3}, {%4,%5,%6,%7}, {%8,%9}, {%0,%1,%2,%3};"
        : "+f"(c[0]), "+f"(c[1]), "+f"(c[2]), "+f"(c[3])
        : "r"(a[0]), "r"(a[1]), "r"(a[2]), "r"(a[3]), "r"(b0), "r"(b1));
}
__device__ __forceinline__ void mbar_init(uint32_t mb, uint32_t cnt) {
    asm volatile("mbarrier.init.shared.b64 [%0], %1;" :: "r"(mb), "r"(cnt) : "memory");
}
__device__ __forceinline__ void bulk_fetch(uint32_t dst, const void* src, uint32_t mb) {
    asm volatile("mbarrier.arrive.expect_tx.shared.b64 _, [%0], %1;"
                 :: "r"(mb), "r"((uint32_t)STAGE_BYTES) : "memory");
    asm volatile("cp.async.bulk.shared::cta.global.mbarrier::complete_tx::bytes "
                 "[%0], [%1], %2, [%3];"
                 :: "r"(dst), "l"(src), "r"((uint32_t)STAGE_BYTES), "r"(mb) : "memory");
}
__device__ __forceinline__ void mbar_wait(uint32_t mb, uint32_t parity) {
    uint32_t done;
    asm volatile(
        "{\n\t.reg .pred p;\n\t"
        "mbarrier.try_wait.parity.shared.b64 p, [%1], %2;\n\t"
        "selp.b32 %0, 1, 0, p;\n\t}"
        : "=r"(done) : "r"(mb), "r"(parity) : "memory");
    while (!done) {
        asm volatile(
            "{\n\t.reg .pred p;\n\t"
            "mbarrier.try_wait.parity.shared.b64 p, [%1], %2;\n\t"
            "selp.b32 %0, 1, 0, p;\n\t}"
            : "=r"(done) : "r"(mb), "r"(parity) : "memory");
    }
}

#define SWZ(off) ((off) ^ (((off) >> 3) & 0x70))

// ---------------------------------------------------------------------------
// SMEM layout (per CTA, bytes). CTA tile: 64 pix x 256 o. 2 CTAs/SM.
// 3-stage B pipeline (bulk-DMA). Prologue temps overlay B stages.
// ---------------------------------------------------------------------------
#define OFF_P1   0          // p1 tile [m][pix] 64x64 fp16 = 8192
#define OFF_B0   8192       // B stages: 32768 each (SW128)
#define OFF_B1   40960
#define OFF_B2   73728
#define OFF_MBAR 106496     // 3 x 8B mbarriers
#define SMEM_TOTAL 106560
#define P2S_STRIDE 68       // p2s tmp [pix][d] fp32, padded row stride
// Epilogue D tile reuses [0, 66048): 64 rows x 258 fp32 (padded stride)
#define DSTRIDE  258

// ---------------------------------------------------------------------------
// Wp -> fp16 in chunk-major pre-swizzled stage layout.
// ---------------------------------------------------------------------------
__global__ void wsplit_kernel(const float* __restrict__ Wp) {
    int idx = blockIdx.x * 256 + threadIdx.x;   // over OUTC*KTOT
    int o = idx >> 12;          // / KTOT
    int k = idx & (KTOT - 1);
    int ch  = k >> 6;
    int d   = k & 63;
    int seg = d >> 3;
    int w   = d & 7;
    size_t dst = (size_t)ch * STAGE_BYTES + SWZ((uint32_t)(o * 128 + seg * 16)) + w * 2;
    *(__half*)((char*)g_Whs + dst) = __float2half_rn(Wp[idx]);
}

// ---------------------------------------------------------------------------
// GEMM partial kernel: in-CTA projections + fp16 mma.sync over one K-third.
// grid = (392 tiles, 3 thirds). CTA: 64 pix x 256 o. 256 thr = 8 warps.
// Writes fp32 partial sums to g_part[third].
// ---------------------------------------------------------------------------
__global__ __launch_bounds__(256, 2)
void bilinear_mma_kernel(const float* __restrict__ x1,
                         const float* __restrict__ x2,
                         const float* __restrict__ W1,
                         const float* __restrict__ W2) {
    extern __shared__ char smem[];
    const uint32_t sbase = smem_u32(smem);

    const int t   = threadIdx.x;
    const int wid = t >> 5;
    const int lid = t & 31;
    const int wp  = wid >> 2;   // pixel group: rows wp*32   (0..1)
    const int wo  = wid & 3;    // o group: cols wo*64       (0..3)
    const int g   = lid >> 2;   // fragment row within 8
    const int q2  = (lid & 3) * 2;
    const int pix0 = blockIdx.x * PIXT;
    const int third = blockIdx.y;
    const int ch0 = (third == 0) ? 0 : (third == 1 ? 22 : 43);
    const int nch = (third == 0) ? 22 : 21;
    const int b   = pix0 / HW;
    const int hw0 = pix0 - b * HW;

    if (t == 0) {
        mbar_init(sbase + OFF_MBAR, 1);
        mbar_init(sbase + OFF_MBAR + 8, 1);
        mbar_init(sbase + OFF_MBAR + 16, 1);
    }

    // ===================== in-CTA projection phase =====================
    float* Ws1 = (float*)(smem + OFF_B0);
    float* Ws2 = (float*)(smem + OFF_B1);
    for (int idx = t; idx < MID * CIN; idx += 256) {
        int c = idx >> 6;
        int m = idx & 63;
        Ws1[idx] = __ldg(&W1[m * CIN + c]);
        Ws2[idx] = __ldg(&W2[m * CIN + c]);
    }
    __syncthreads();

    const int tx = t & 15;    // pixel quad: pixels tx*4..+3
    const int ty = t >> 4;    // m quad:     m = ty*4..+3

    __half* p1s = (__half*)(smem + OFF_P1);       // [m][pix] fp16
    float*  p2s = (float*)(smem + OFF_B2);        // [pix][d] fp32, stride 68

    {
        const float* xb1 = x1 + (size_t)b * CIN * HW + hw0 + tx * 4;
        const float* xb2 = x2 + (size_t)b * CIN * HW + hw0 + tx * 4;

        float a1[4][4], a2[4][4];
#pragma unroll
        for (int mi = 0; mi < 4; mi++)
#pragma unroll
            for (int pi = 0; pi < 4; pi++) { a1[mi][pi] = 0.0f; a2[mi][pi] = 0.0f; }

#pragma unroll 4
        for (int c = 0; c < CIN; c++) {
            float4 xv1 = *(const float4*)(xb1 + (size_t)c * HW);
            float4 xv2 = *(const float4*)(xb2 + (size_t)c * HW);
            float4 wv1 = *(const float4*)&Ws1[c * 64 + ty * 4];
            float4 wv2 = *(const float4*)&Ws2[c * 64 + ty * 4];
            float xs1[4] = {xv1.x, xv1.y, xv1.z, xv1.w};
            float xs2[4] = {xv2.x, xv2.y, xv2.z, xv2.w};
            float w1v[4] = {wv1.x, wv1.y, wv1.z, wv1.w};
            float w2v[4] = {wv2.x, wv2.y, wv2.z, wv2.w};
#pragma unroll
            for (int mi = 0; mi < 4; mi++)
#pragma unroll
                for (int pi = 0; pi < 4; pi++) {
                    a1[mi][pi] += w1v[mi] * xs1[pi];
                    a2[mi][pi] += w2v[mi] * xs2[pi];
                }
        }
        __syncthreads();   // Ws reads done

        // p1 -> p1s fp16 [m][pix]
#pragma unroll
        for (int mi = 0; mi < 4; mi++)
#pragma unroll
            for (int pi = 0; pi < 4; pi++)
                p1s[(ty * 4 + mi) * PIXT + tx * 4 + pi] = __float2half_rn(a1[mi][pi]);

        // p2 -> p2s fp32 [pix][d] (temp in B2 region)
#pragma unroll
        for (int pi = 0; pi < 4; pi++)
#pragma unroll
            for (int mi = 0; mi < 4; mi++)
                p2s[(tx * 4 + pi) * P2S_STRIDE + ty * 4 + mi] = a2[mi][pi];
    }
    __syncthreads();   // p1s + p2s published

    // p2 persistent fragment regs (packed half2)
    uint32_t p2f[32];
#pragma unroll
    for (int mt = 0; mt < 2; mt++)
#pragma unroll
        for (int h = 0; h < 2; h++) {
            const float* prow = p2s + (wp * 32 + mt * 16 + h * 8 + g) * P2S_STRIDE;
#pragma unroll
            for (int kk = 0; kk < 4; kk++)
#pragma unroll
                for (int j = 0; j < 2; j++) {
                    float2 v = *(const float2*)&prow[kk * 16 + q2 + j * 8];
                    p2f[((mt * 2 + h) * 4 + kk) * 2 + j] =
                        h2_u32(__floats2half2_rn(v.x, v.y));
                }
        }
    __syncthreads();   // p2s reads complete; B regions free; mbars visible

    // ===================== mainloop over this K-third =====================
    const uint32_t offB[3] = {OFF_B0, OFF_B1, OFF_B2};

    float acc[2][8][4];
#pragma unroll
    for (int mt = 0; mt < 2; mt++)
#pragma unroll
        for (int nt = 0; nt < 8; nt++)
#pragma unroll
            for (int i = 0; i < 4; i++) acc[mt][nt][i] = 0.0f;

    // Prologue: local chunks 0 and 1 in flight
    if (t == 0) {
        bulk_fetch(sbase + OFF_B0,
                   (const char*)g_Whs + (size_t)ch0 * STAGE_BYTES, sbase + OFF_MBAR);
        bulk_fetch(sbase + OFF_B1,
                   (const char*)g_Whs + (size_t)(ch0 + 1) * STAGE_BYTES, sbase + OFF_MBAR + 8);
    }

    const int b_row_l = ((lid >> 4) << 3) + (lid & 7);
    const int b_hi16  = ((lid >> 3) & 1) * 16;

    for (int i = 0; i < nch; i++) {
        const int s = i % 3;
        const int ch = ch0 + i;   // global chunk

        if (t == 0 && i + 2 < nch) {
            int s2 = (i + 2) % 3;
            bulk_fetch(sbase + offB[s2],
                       (const char*)g_Whs + (size_t)(ch + 2) * STAGE_BYTES,
                       sbase + OFF_MBAR + s2 * 8);
        }

        mbar_wait(sbase + OFF_MBAR + s * 8, (i / 3) & 1);

        // p1 scalars for this chunk (fp16, broadcast LDS within quads)
        uint32_t p1h2[2][2];
#pragma unroll
        for (int mt = 0; mt < 2; mt++)
#pragma unroll
            for (int h = 0; h < 2; h++)
                p1h2[mt][h] = h2_u32(__half2half2(
                    p1s[ch * PIXT + wp * 32 + mt * 16 + h * 8 + g]));

        const uint32_t bb = sbase + offB[s];
#pragma unroll
        for (int kk = 0; kk < 4; kk++) {
            uint32_t afr[2][4];
#pragma unroll
            for (int mt = 0; mt < 2; mt++)
#pragma unroll
                for (int rr = 0; rr < 4; rr++) {
                    int h = rr & 1, j = rr >> 1;
                    afr[mt][rr] = h2_u32(__hmul2(
                        u32_h2(p1h2[mt][h]),
                        u32_h2(p2f[((mt * 2 + h) * 4 + kk) * 2 + j])));
                }

#pragma unroll
            for (int bp = 0; bp < 4; bp++) {
                int orow = wo * 64 + bp * 16 + b_row_l;
                uint32_t addr = bb + SWZ((uint32_t)(orow * 128 + kk * 32 + b_hi16));
                uint32_t r0, r1, r2, r3;
                ldsm_x4(r0, r1, r2, r3, addr);
                mma16816(acc[0][bp * 2],     afr[0], r0, r1);
                mma16816(acc[1][bp * 2],     afr[1], r0, r1);
                mma16816(acc[0][bp * 2 + 1], afr[0], r2, r3);
                mma16816(acc[1][bp * 2 + 1], afr[1], r2, r3);
            }
        }

        __syncthreads();   // stage s consumed before tid0 refills it
    }

    // --- stage acc -> smem D, then coalesced fp32 partial store ---
    float* D = (float*)smem;
#pragma unroll
    for (int mt = 0; mt < 2; mt++) {
#pragma unroll
        for (int nt = 0; nt < 8; nt++) {
            int row = wp * 32 + mt * 16 + (lid >> 2);
            int col = wo * 64 + nt * 8 + (lid & 3) * 2;
            *(float2*)&D[row * DSTRIDE + col] = make_float2(acc[mt][nt][0], acc[mt][nt][1]);
            *(float2*)&D[(row + 8) * DSTRIDE + col] = make_float2(acc[mt][nt][2], acc[mt][nt][3]);
        }
    }
    __syncthreads();

    {
        float* pbase = g_part + ((size_t)third * NPIX + pix0) * OUTC;
#pragma unroll
        for (int r = 0; r < 32; r++) {
            int idx2 = t + r * 256;          // 0..8191 float2 slots
            int pix  = idx2 >> 7;            // 128 float2 per 256-float row
            int o2   = idx2 & 127;
            float2 v = *(const float2*)&D[pix * DSTRIDE + o2 * 2];
            *(float2*)&pbase[pix * OUTC + o2 * 2] = v;
        }
    }
}

// ---------------------------------------------------------------------------
// LN + exact GELU epilogue: sum 3 K-partials, normalize, store NCHW.
// grid 392, 256 threads; thread = (pixel, quarter of 256 channels).
// ---------------------------------------------------------------------------
__global__ __launch_bounds__(256)
void ln_gelu_kernel(const float* __restrict__ gamma,
                    const float* __restrict__ beta,
                    float* __restrict__ out) {
    const int t   = threadIdx.x;
    const int pix = t >> 2;       // 0..63
    const int q   = t & 3;
    const int P   = blockIdx.x * PIXT + pix;
    const int bb  = P / HW;
    const int hw  = P - bb * HW;

    float v[64];
    {
        const float* p0 = g_part + ((size_t)0 * NPIX + P) * OUTC + q * 64;
        const float* p1 = g_part + ((size_t)1 * NPIX + P) * OUTC + q * 64;
        const float* p2 = g_part + ((size_t)2 * NPIX + P) * OUTC + q * 64;
#pragma unroll
        for (int j = 0; j < 16; j++) {
            float4 a = *(const float4*)&p0[j * 4];
            float4 bq = *(const float4*)&p1[j * 4];
            float4 c = *(const float4*)&p2[j * 4];
            v[j * 4 + 0] = a.x + bq.x + c.x;
            v[j * 4 + 1] = a.y + bq.y + c.y;
            v[j * 4 + 2] = a.z + bq.z + c.z;
            v[j * 4 + 3] = a.w + bq.w + c.w;
        }
    }

    float s1 = 0.0f, s2 = 0.0f;
#pragma unroll
    for (int j = 0; j < 64; j++) {
        s1 += v[j];
        s2 += v[j] * v[j];
    }
    s1 += __shfl_xor_sync(0xffffffffu, s1, 1);
    s2 += __shfl_xor_sync(0xffffffffu, s2, 1);
    s1 += __shfl_xor_sync(0xffffffffu, s1, 2);
    s2 += __shfl_xor_sync(0xffffffffu, s2, 2);

    float mu = s1 * (1.0f / OUTC);
    float var = s2 * (1.0f / OUTC) - mu * mu;
    float rs = rsqrtf(var + EPS);

    float* obase = out + (size_t)bb * OUTC * HW + hw;
#pragma unroll
    for (int j = 0; j < 64; j++) {
        int o = q * 64 + j;
        float x = (v[j] - mu) * rs * __ldg(&gamma[o]) + __ldg(&beta[o]);
        float y = 0.5f * x * (1.0f + erff(x * 0.70710678118654752f));
        obase[(size_t)o * HW] = y;
    }
}

// ---------------------------------------------------------------------------
extern "C" void kernel_launch(void* const* d_in, const int* in_sizes, int n_in,
                              void* d_out, int out_size) {
    const float* x1    = (const float*)d_in[0];
    const float* x2    = (const float*)d_in[1];
    const float* W1    = (const float*)d_in[2];
    const float* W2    = (const float*)d_in[3];
    const float* Wp    = (const float*)d_in[4];
    const float* gamma = (const float*)d_in[5];
    const float* beta  = (const float*)d_in[6];
    float* out = (float*)d_out;

    static bool attr_done = false;
    if (!attr_done) {
        cudaFuncSetAttribute(bilinear_mma_kernel,
                             cudaFuncAttributeMaxDynamicSharedMemorySize, SMEM_TOTAL);
        attr_done = true;
    }

    wsplit_kernel<<<(OUTC * KTOT) / 256, 256>>>(Wp);
    bilinear_mma_kernel<<<dim3(NPIX / PIXT, NSPLIT), 256, SMEM_TOTAL>>>(x1, x2, W1, W2);
    ln_gelu_kernel<<<NPIX / PIXT, 256>>>(gamma, beta, out);
}

// round 15
// speedup vs baseline: 1.5680x; 1.5680x over previous
#include <cuda_runtime.h>
#include <cuda_fp16.h>
#include <cstdint>
#include <math.h>

// Problem constants
#define BATCH 8
#define CIN   128
#define HW    3136        // 56*56
#define NPIX  25088       // 8*3136
#define MID   64
#define OUTC  256
#define KTOT  4096        // 64*64
#define EPS   1e-5f
#define PIXT  64          // pixels per CTA tile
#define STAGE_BYTES 32768 // one B chunk stage: 256 o x 64 d fp16, SW128

// Scratch: Wp in fp16, CHUNK-MAJOR PRE-SWIZZLED stage layout.
__device__ __align__(128) __half g_Whs[(size_t)OUTC * KTOT];

// ---------------------------------------------------------------------------
// Helpers (base-arch PTX only: cp.async.bulk / mbarrier / ldmatrix / mma.sync)
// ---------------------------------------------------------------------------
__device__ __forceinline__ uint32_t smem_u32(const void* p) {
    uint32_t a;
    asm("{ .reg .u64 t; cvta.to.shared.u64 t, %1; cvt.u32.u64 %0, t; }" : "=r"(a) : "l"(p));
    return a;
}
__device__ __forceinline__ uint32_t h2_u32(__half2 h) {
    union { __half2 h; uint32_t u; } cv;
    cv.h = h;
    return cv.u;
}
__device__ __forceinline__ __half2 u32_h2(uint32_t u) {
    union { __half2 h; uint32_t u; } cv;
    cv.u = u;
    return cv.h;
}
__device__ __forceinline__ void ldsm_x4(uint32_t& r0, uint32_t& r1, uint32_t& r2, uint32_t& r3,
                                        uint32_t addr) {
    asm volatile("ldmatrix.sync.aligned.m8n8.x4.shared.b16 {%0,%1,%2,%3}, [%4];"
                 : "=r"(r0), "=r"(r1), "=r"(r2), "=r"(r3) : "r"(addr));
}
__device__ __forceinline__ void mma16816(float* c, const uint32_t* a, uint32_t b0, uint32_t b1) {
    asm volatile(
        "mma.sync.aligned.m16n8k16.row.col.f32.f16.f16.f32 "
        "{%0,%1,%2,%3}, {%4,%5,%6,%7}, {%8,%9}, {%0,%1,%2,%3};"
        : "+f"(c[0]), "+f"(c[1]), "+f"(c[2]), "+f"(c[3])
        : "r"(a[0]), "r"(a[1]), "r"(a[2]), "r"(a[3]), "r"(b0), "r"(b1));
}
__device__ __forceinline__ void mbar_init(uint32_t mb, uint32_t cnt) {
    asm volatile("mbarrier.init.shared.b64 [%0], %1;" :: "r"(mb), "r"(cnt) : "memory");
}
__device__ __forceinline__ void bulk_fetch(uint32_t dst, const void* src, uint32_t mb) {
    asm volatile("mbarrier.arrive.expect_tx.shared.b64 _, [%0], %1;"
                 :: "r"(mb), "r"((uint32_t)STAGE_BYTES) : "memory");
    asm volatile("cp.async.bulk.shared::cta.global.mbarrier::complete_tx::bytes "
                 "[%0], [%1], %2, [%3];"
                 :: "r"(dst), "l"(src), "r"((uint32_t)STAGE_BYTES), "r"(mb) : "memory");
}
__device__ __forceinline__ void mbar_wait(uint32_t mb, uint32_t parity) {
    uint32_t done;
    asm volatile(
        "{\n\t.reg .pred p;\n\t"
        "mbarrier.try_wait.parity.shared.b64 p, [%1], %2;\n\t"
        "selp.b32 %0, 1, 0, p;\n\t}"
        : "=r"(done) : "r"(mb), "r"(parity) : "memory");
    while (!done) {
        asm volatile(
            "{\n\t.reg .pred p;\n\t"
            "mbarrier.try_wait.parity.shared.b64 p, [%1], %2;\n\t"
            "selp.b32 %0, 1, 0, p;\n\t}"
            : "=r"(done) : "r"(mb), "r"(parity) : "memory");
    }
}

#define SWZ(off) ((off) ^ (((off) >> 3) & 0x70))

// ---------------------------------------------------------------------------
// SMEM layout (per CTA, bytes). CTA tile: 64 pix x 256 o. 2 CTAs/SM.
// 3-stage B pipeline (bulk-DMA). Proj uses ONE Ws buffer (B0, two passes) so
// B1 can prefetch chunk 0 during proj. p2s temp -> B2.
// Stage rotation: ch%3 -> {B1, B2, B0}.
// ---------------------------------------------------------------------------
#define OFF_P1   0          // p1 tile [m][pix] 64x64 fp16 = 8192
#define OFF_B0   8192       // B stages: 32768 each (SW128)
#define OFF_B1   40960
#define OFF_B2   73728
#define OFF_GB   106496     // gamma 256 + beta 256 fp32 = 2048
#define OFF_MBAR 108544     // 3 x 8B mbarriers (indexed by ch%3)
#define SMEM_TOTAL 108608
#define P2S_STRIDE 68       // p2s tmp [pix][d] fp32, padded row stride
// Epilogue D tile reuses [0, 66048): 64 rows x 258 fp32 (padded stride)
#define DSTRIDE  258

// ---------------------------------------------------------------------------
// Wp -> fp16 in chunk-major pre-swizzled stage layout.
// ---------------------------------------------------------------------------
__global__ void wsplit_kernel(const float* __restrict__ Wp) {
    int idx = blockIdx.x * 256 + threadIdx.x;   // over OUTC*KTOT
    int o = idx >> 12;          // / KTOT
    int k = idx & (KTOT - 1);
    int ch  = k >> 6;
    int d   = k & 63;
    int seg = d >> 3;
    int w   = d & 7;
    size_t dst = (size_t)ch * STAGE_BYTES + SWZ((uint32_t)(o * 128 + seg * 16)) + w * 2;
    *(__half*)((char*)g_Whs + dst) = __float2half_rn(Wp[idx]);
}

// ---------------------------------------------------------------------------
// Fused: in-CTA projections (2-pass, DMA-overlapped) + fp16 mma.sync GEMM +
// LN + exact GELU. CTA: 64 pix x 256 o. 256 threads = 8 warps (2 pix x 4 o).
// ---------------------------------------------------------------------------
__global__ __launch_bounds__(256, 2)
void bilinear_mma_kernel(const float* __restrict__ x1,
                         const float* __restrict__ x2,
                         const float* __restrict__ W1,
                         const float* __restrict__ W2,
                         const float* __restrict__ gamma,
                         const float* __restrict__ beta,
                         float* __restrict__ out) {
    extern __shared__ char smem[];
    const uint32_t sbase = smem_u32(smem);

    const int t   = threadIdx.x;
    const int wid = t >> 5;
    const int lid = t & 31;
    const int wp  = wid >> 2;   // pixel group: rows wp*32   (0..1)
    const int wo  = wid & 3;    // o group: cols wo*64       (0..3)
    const int g   = lid >> 2;   // fragment row within 8
    const int q2  = (lid & 3) * 2;
    const int pix0 = blockIdx.x * PIXT;
    const int b   = pix0 / HW;
    const int hw0 = pix0 - b * HW;

    // mbarriers; then tid0 immediately prefetches chunk 0 into B1 (free now).
    if (t == 0) {
        mbar_init(sbase + OFF_MBAR, 1);
        mbar_init(sbase + OFF_MBAR + 8, 1);
        mbar_init(sbase + OFF_MBAR + 16, 1);
        bulk_fetch(sbase + OFF_B1, (const char*)g_Whs, sbase + OFF_MBAR);
    }
    {
        float* gb = (float*)(smem + OFF_GB);
        gb[t]       = __ldg(&gamma[t]);
        gb[256 + t] = __ldg(&beta[t]);
    }

    // ============= in-CTA projection phase (single Ws buffer, 2 passes) ====
    float* Ws = (float*)(smem + OFF_B0);
    const int tx = t & 15;    // pixel quad: pixels tx*4..+3
    const int ty = t >> 4;    // m quad:     m = ty*4..+3

    __half* p1s = (__half*)(smem + OFF_P1);       // [m][pix] fp16
    float*  p2s = (float*)(smem + OFF_B2);        // [pix][d] fp32, stride 68

    // ---- pass 1: p1 = W1 * x1 ----
    for (int idx = t; idx < MID * CIN; idx += 256) {
        int c = idx >> 6;
        int m = idx & 63;
        Ws[idx] = __ldg(&W1[m * CIN + c]);
    }
    __syncthreads();
    {
        const float* xb1 = x1 + (size_t)b * CIN * HW + hw0 + tx * 4;
        float a1[4][4];
#pragma unroll
        for (int mi = 0; mi < 4; mi++)
#pragma unroll
            for (int pi = 0; pi < 4; pi++) a1[mi][pi] = 0.0f;
#pragma unroll 4
        for (int c = 0; c < CIN; c++) {
            float4 xv1 = *(const float4*)(xb1 + (size_t)c * HW);
            float4 wv1 = *(const float4*)&Ws[c * 64 + ty * 4];
            float xs1[4] = {xv1.x, xv1.y, xv1.z, xv1.w};
            float w1v[4] = {wv1.x, wv1.y, wv1.z, wv1.w};
#pragma unroll
            for (int mi = 0; mi < 4; mi++)
#pragma unroll
                for (int pi = 0; pi < 4; pi++)
                    a1[mi][pi] += w1v[mi] * xs1[pi];
        }
#pragma unroll
        for (int mi = 0; mi < 4; mi++)
#pragma unroll
            for (int pi = 0; pi < 4; pi++)
                p1s[(ty * 4 + mi) * PIXT + tx * 4 + pi] = __float2half_rn(a1[mi][pi]);
    }
    __syncthreads();   // Ws pass-1 reads done

    // ---- pass 2: p2 = W2 * x2 ----
    for (int idx = t; idx < MID * CIN; idx += 256) {
        int c = idx >> 6;
        int m = idx & 63;
        Ws[idx] = __ldg(&W2[m * CIN + c]);
    }
    __syncthreads();
    {
        const float* xb2 = x2 + (size_t)b * CIN * HW + hw0 + tx * 4;
        float a2[4][4];
#pragma unroll
        for (int mi = 0; mi < 4; mi++)
#pragma unroll
            for (int pi = 0; pi < 4; pi++) a2[mi][pi] = 0.0f;
#pragma unroll 4
        for (int c = 0; c < CIN; c++) {
            float4 xv2 = *(const float4*)(xb2 + (size_t)c * HW);
            float4 wv2 = *(const float4*)&Ws[c * 64 + ty * 4];
            float xs2[4] = {xv2.x, xv2.y, xv2.z, xv2.w};
            float w2v[4] = {wv2.x, wv2.y, wv2.z, wv2.w};
#pragma unroll
            for (int mi = 0; mi < 4; mi++)
#pragma unroll
                for (int pi = 0; pi < 4; pi++)
                    a2[mi][pi] += w2v[mi] * xs2[pi];
        }
#pragma unroll
        for (int pi = 0; pi < 4; pi++)
#pragma unroll
            for (int mi = 0; mi < 4; mi++)
                p2s[(tx * 4 + pi) * P2S_STRIDE + ty * 4 + mi] = a2[mi][pi];
    }
    __syncthreads();   // p1s + p2s published

    // p2 persistent fragment regs (packed half2)
    uint32_t p2f[32];
#pragma unroll
    for (int mt = 0; mt < 2; mt++)
#pragma unroll
        for (int h = 0; h < 2; h++) {
            const float* prow = p2s + (wp * 32 + mt * 16 + h * 8 + g) * P2S_STRIDE;
#pragma unroll
            for (int kk = 0; kk < 4; kk++)
#pragma unroll
                for (int j = 0; j < 2; j++) {
                    float2 v = *(const float2*)&prow[kk * 16 + q2 + j * 8];
                    p2f[((mt * 2 + h) * 4 + kk) * 2 + j] =
                        h2_u32(__floats2half2_rn(v.x, v.y));
                }
        }
    __syncthreads();   // p2s reads complete; B0/B2 free

    // ===================== mainloop =====================
    // Stage rotation: ch%3 -> {B1, B2, B0}; mbar s = ch%3.
    const uint32_t offB[3] = {OFF_B1, OFF_B2, OFF_B0};

    float acc[2][8][4];
#pragma unroll
    for (int mt = 0; mt < 2; mt++)
#pragma unroll
        for (int nt = 0; nt < 8; nt++)
#pragma unroll
            for (int i = 0; i < 4; i++) acc[mt][nt][i] = 0.0f;

    // chunk 0 already in flight since kernel start; issue 1 and 2 now.
    if (t == 0) {
        bulk_fetch(sbase + OFF_B2, (const char*)g_Whs + STAGE_BYTES,
                   sbase + OFF_MBAR + 8);
        bulk_fetch(sbase + OFF_B0, (const char*)g_Whs + 2 * (size_t)STAGE_BYTES,
                   sbase + OFF_MBAR + 16);
    }

    const int b_row_l = ((lid >> 4) << 3) + (lid & 7);
    const int b_hi16  = ((lid >> 3) & 1) * 16;

    for (int ch = 0; ch < 64; ch++) {
        const int s = ch % 3;

        // refetch: chunk ch+2 into its stage (freed at end of chunk ch-1)
        if (t == 0 && ch >= 1 && ch < 62) {
            int s2 = (ch + 2) % 3;
            bulk_fetch(sbase + offB[s2],
                       (const char*)g_Whs + (size_t)(ch + 2) * STAGE_BYTES,
                       sbase + OFF_MBAR + s2 * 8);
        }

        mbar_wait(sbase + OFF_MBAR + s * 8, (ch / 3) & 1);

        // p1 scalars for this chunk (fp16, broadcast LDS within quads)
        uint32_t p1h2[2][2];
#pragma unroll
        for (int mt = 0; mt < 2; mt++)
#pragma unroll
            for (int h = 0; h < 2; h++)
                p1h2[mt][h] = h2_u32(__half2half2(
                    p1s[ch * PIXT + wp * 32 + mt * 16 + h * 8 + g]));

        const uint32_t bb = sbase + offB[s];
#pragma unroll
        for (int kk = 0; kk < 4; kk++) {
            // Batch all 4 B-ldsm first (independent, latency overlapped)
            uint32_t bfr[4][4];
#pragma unroll
            for (int bp = 0; bp < 4; bp++) {
                int orow = wo * 64 + bp * 16 + b_row_l;
                uint32_t addr = bb + SWZ((uint32_t)(orow * 128 + kk * 32 + b_hi16));
                ldsm_x4(bfr[bp][0], bfr[bp][1], bfr[bp][2], bfr[bp][3], addr);
            }
            // afr build (covers ldsm latency)
            uint32_t afr[2][4];
#pragma unroll
            for (int mt = 0; mt < 2; mt++)
#pragma unroll
                for (int rr = 0; rr < 4; rr++) {
                    int h = rr & 1, j = rr >> 1;
                    afr[mt][rr] = h2_u32(__hmul2(
                        u32_h2(p1h2[mt][h]),
                        u32_h2(p2f[((mt * 2 + h) * 4 + kk) * 2 + j])));
                }
            // MMAs
#pragma unroll
            for (int bp = 0; bp < 4; bp++) {
                mma16816(acc[0][bp * 2],     afr[0], bfr[bp][0], bfr[bp][1]);
                mma16816(acc[1][bp * 2],     afr[1], bfr[bp][0], bfr[bp][1]);
                mma16816(acc[0][bp * 2 + 1], afr[0], bfr[bp][2], bfr[bp][3]);
                mma16816(acc[1][bp * 2 + 1], afr[1], bfr[bp][2], bfr[bp][3]);
            }
        }

        __syncthreads();   // stage s consumed before tid0 refills it
    }

    // --- epilogue: acc -> smem D, per-pixel LN + GELU + store ---
    float* D = (float*)smem;
#pragma unroll
    for (int mt = 0; mt < 2; mt++) {
#pragma unroll
        for (int nt = 0; nt < 8; nt++) {
            int row = wp * 32 + mt * 16 + (lid >> 2);
            int col = wo * 64 + nt * 8 + (lid & 3) * 2;
            *(float2*)&D[row * DSTRIDE + col] = make_float2(acc[mt][nt][0], acc[mt][nt][1]);
            *(float2*)&D[(row + 8) * DSTRIDE + col] = make_float2(acc[mt][nt][2], acc[mt][nt][3]);
        }
    }
    __syncthreads();

    {
        const int pix = t >> 2;   // 0..63
        const int q   = t & 3;
        const float* Drow = D + pix * DSTRIDE + q * 64;
        float s1 = 0.0f, s2 = 0.0f;
#pragma unroll
        for (int j = 0; j < 32; j++) {
            float2 v = *(const float2*)&Drow[j * 2];
            s1 += v.x + v.y;
            s2 += v.x * v.x + v.y * v.y;
        }
        s1 += __shfl_xor_sync(0xffffffffu, s1, 1);
        s2 += __shfl_xor_sync(0xffffffffu, s2, 1);
        s1 += __shfl_xor_sync(0xffffffffu, s1, 2);
        s2 += __shfl_xor_sync(0xffffffffu, s2, 2);

        float mu = s1 * (1.0f / OUTC);
        float var = s2 * (1.0f / OUTC) - mu * mu;
        float rs = rsqrtf(var + EPS);

        const int P  = pix0 + pix;
        const int bb2 = P / HW;
        const int hw = P - bb2 * HW;
        float* obase = out + (size_t)bb2 * OUTC * HW + hw;
        const float* sg  = (const float*)(smem + OFF_GB);
        const float* sbt = sg + 256;

#pragma unroll
        for (int j = 0; j < 64; j++) {
            int o = q * 64 + j;
            float x = (Drow[j] - mu) * rs * sg[o] + sbt[o];
            float y = 0.5f * x * (1.0f + erff(x * 0.70710678118654752f));
            obase[(size_t)o * HW] = y;
        }
    }
}

// ---------------------------------------------------------------------------
extern "C" void kernel_launch(void* const* d_in, const int* in_sizes, int n_in,
                              void* d_out, int out_size) {
    const float* x1    = (const float*)d_in[0];
    const float* x2    = (const float*)d_in[1];
    const float* W1    = (const float*)d_in[2];
    const float* W2    = (const float*)d_in[3];
    const float* Wp    = (const float*)d_in[4];
    const float* gamma = (const float*)d_in[5];
    const float* beta  = (const float*)d_in[6];
    float* out = (float*)d_out;

    static bool attr_done = false;
    if (!attr_done) {
        cudaFuncSetAttribute(bilinear_mma_kernel,
                             cudaFuncAttributeMaxDynamicSharedMemorySize, SMEM_TOTAL);
        attr_done = true;
    }

    wsplit_kernel<<<(OUTC * KTOT) / 256, 256>>>(Wp);
    bilinear_mma_kernel<<<NPIX / PIXT, 256, SMEM_TOTAL>>>(x1, x2, W1, W2, gamma, beta, out);
}

// round 16
// speedup vs baseline: 1.8663x; 1.1902x over previous
#include <cuda_runtime.h>
#include <cuda_fp16.h>
#include <cstdint>
#include <math.h>

// Problem constants
#define BATCH 8
#define CIN   128
#define HW    3136        // 56*56
#define NPIX  25088       // 8*3136
#define MID   64
#define OUTC  256
#define KTOT  4096        // 64*64
#define EPS   1e-5f
#define PIXT  64          // pixels per CTA tile
#define STAGE_BYTES 32768 // one B chunk stage: 256 o x 64 d fp16, SW128

// Scratch: Wp in fp16, CHUNK-MAJOR PRE-SWIZZLED stage layout.
__device__ __align__(128) __half g_Whs[(size_t)OUTC * KTOT];

// ---------------------------------------------------------------------------
// Helpers (base-arch PTX only: cp.async.bulk / mbarrier / ldmatrix / mma.sync)
// ---------------------------------------------------------------------------
__device__ __forceinline__ uint32_t smem_u32(const void* p) {
    uint32_t a;
    asm("{ .reg .u64 t; cvta.to.shared.u64 t, %1; cvt.u32.u64 %0, t; }" : "=r"(a) : "l"(p));
    return a;
}
__device__ __forceinline__ uint32_t h2_u32(__half2 h) {
    union { __half2 h; uint32_t u; } cv;
    cv.h = h;
    return cv.u;
}
__device__ __forceinline__ __half2 u32_h2(uint32_t u) {
    union { __half2 h; uint32_t u; } cv;
    cv.u = u;
    return cv.h;
}
__device__ __forceinline__ void ldsm_x4(uint32_t& r0, uint32_t& r1, uint32_t& r2, uint32_t& r3,
                                        uint32_t addr) {
    asm volatile("ldmatrix.sync.aligned.m8n8.x4.shared.b16 {%0,%1,%2,%3}, [%4];"
                 : "=r"(r0), "=r"(r1), "=r"(r2), "=r"(r3) : "r"(addr));
}
__device__ __forceinline__ void mma16816(float* c, const uint32_t* a, uint32_t b0, uint32_t b1) {
    asm volatile(
        "mma.sync.aligned.m16n8k16.row.col.f32.f16.f16.f32 "
        "{%0,%1,%2,%3}, {%4,%5,%6,%7}, {%8,%9}, {%0,%1,%2,%3};"
        : "+f"(c[0]), "+f"(c[1]), "+f"(c[2]), "+f"(c[3])
        : "r"(a[0]), "r"(a[1]), "r"(a[2]), "r"(a[3]), "r"(b0), "r"(b1));
}
__device__ __forceinline__ void mbar_init(uint32_t mb, uint32_t cnt) {
    asm volatile("mbarrier.init.shared.b64 [%0], %1;" :: "r"(mb), "r"(cnt) : "memory");
}
__device__ __forceinline__ void bulk_fetch(uint32_t dst, const void* src, uint32_t mb) {
    asm volatile("mbarrier.arrive.expect_tx.shared.b64 _, [%0], %1;"
                 :: "r"(mb), "r"((uint32_t)STAGE_BYTES) : "memory");
    asm volatile("cp.async.bulk.shared::cta.global.mbarrier::complete_tx::bytes "
                 "[%0], [%1], %2, [%3];"
                 :: "r"(dst), "l"(src), "r"((uint32_t)STAGE_BYTES), "r"(mb) : "memory");
}
__device__ __forceinline__ void mbar_wait(uint32_t mb, uint32_t parity) {
    uint32_t done;
    asm volatile(
        "{\n\t.reg .pred p;\n\t"
        "mbarrier.try_wait.parity.shared.b64 p, [%1], %2;\n\t"
        "selp.b32 %0, 1, 0, p;\n\t}"
        : "=r"(done) : "r"(mb), "r"(parity) : "memory");
    while (!done) {
        asm volatile(
            "{\n\t.reg .pred p;\n\t"
            "mbarrier.try_wait.parity.shared.b64 p, [%1], %2;\n\t"
            "selp.b32 %0, 1, 0, p;\n\t}"
            : "=r"(done) : "r"(mb), "r"(parity) : "memory");
    }
}

#define SWZ(off) ((off) ^ (((off) >> 3) & 0x70))

// ---------------------------------------------------------------------------
// SMEM layout (per CTA, bytes). CTA tile: 64 pix x 256 o. 2 CTAs/SM.
// Proj phase overlays: W fp16 [2][64][64] + xT fp16 [2][64][64] -> B0 (32KB),
// p2s [d][pix] fp32 stride 66 -> B2. B1 prefetches chunk 0 during proj.
// Stage rotation: ch%3 -> {B1, B2, B0}.
// ---------------------------------------------------------------------------
#define P1S      66         // p1s stride (halves), padded
#define OFF_P1   0          // p1 tile [m][pix] 64x66 fp16 = 8448
#define OFF_B0   8448       // B stages: 32768 each (SW128, 128B aligned)
#define OFF_B1   41216
#define OFF_B2   73984
#define OFF_GB   106752     // gamma 256 + beta 256 fp32 = 2048
#define OFF_MBAR 108800     // 3 x 8B mbarriers
#define SMEM_TOTAL 108832
#define P2SS     66         // p2s stride (floats)
// Epilogue D tile reuses [0, 66048): 64 rows x 258 fp32 (padded stride)
#define DSTRIDE  258

// ---------------------------------------------------------------------------
// Wp -> fp16 in chunk-major pre-swizzled stage layout.
// ---------------------------------------------------------------------------
__global__ void wsplit_kernel(const float* __restrict__ Wp) {
    int idx = blockIdx.x * 256 + threadIdx.x;   // over OUTC*KTOT
    int o = idx >> 12;          // / KTOT
    int k = idx & (KTOT - 1);
    int ch  = k >> 6;
    int d   = k & 63;
    int seg = d >> 3;
    int w   = d & 7;
    size_t dst = (size_t)ch * STAGE_BYTES + SWZ((uint32_t)(o * 128 + seg * 16)) + w * 2;
    *(__half*)((char*)g_Whs + dst) = __float2half_rn(Wp[idx]);
}

// ---------------------------------------------------------------------------
// Fused: tensor-core projections + fp16 mma.sync GEMM + LN + exact GELU.
// CTA: 64 pix x 256 o. 256 threads = 8 warps (2 pix x 4 o groups in GEMM).
// ---------------------------------------------------------------------------
__global__ __launch_bounds__(256, 2)
void bilinear_mma_kernel(const float* __restrict__ x1,
                         const float* __restrict__ x2,
                         const float* __restrict__ W1,
                         const float* __restrict__ W2,
                         const float* __restrict__ gamma,
                         const float* __restrict__ beta,
                         float* __restrict__ out) {
    extern __shared__ char smem[];
    const uint32_t sbase = smem_u32(smem);

    const int t   = threadIdx.x;
    const int wid = t >> 5;
    const int lid = t & 31;
    const int wp  = wid >> 2;   // GEMM pixel group (0..1)
    const int wo  = wid & 3;    // GEMM o group (0..3)
    const int g   = lid >> 2;
    const int q2  = (lid & 3) * 2;
    const int pix0 = blockIdx.x * PIXT;
    const int b   = pix0 / HW;
    const int hw0 = pix0 - b * HW;

    const int a_row_l = lid & 15;
    const int a_hi16  = (lid >> 4) * 16;
    const int b_row_l = ((lid >> 4) << 3) + (lid & 7);
    const int b_hi16  = ((lid >> 3) & 1) * 16;

    // mbarriers; then tid0 immediately prefetches chunk 0 into B1 (free now).
    if (t == 0) {
        mbar_init(sbase + OFF_MBAR, 1);
        mbar_init(sbase + OFF_MBAR + 8, 1);
        mbar_init(sbase + OFF_MBAR + 16, 1);
        bulk_fetch(sbase + OFF_B1, (const char*)g_Whs, sbase + OFF_MBAR);
    }
    {
        float* gb = (float*)(smem + OFF_GB);
        gb[t]       = __ldg(&gamma[t]);
        gb[256 + t] = __ldg(&beta[t]);
    }

    // ===== projection via tensor cores: p = W(64x128) @ x(128x64pix) =======
    __half* p1s = (__half*)(smem + OFF_P1);       // [m][pix] fp16 stride 66
    float*  p2s = (float*)(smem + OFF_B2);        // [d][pix] fp32 stride 66
    const uint32_t sW = sbase + OFF_B0;           // [part][m][c64] fp16 SW128
    const uint32_t sX = sbase + OFF_B0 + 16384;   // [part][pix][c64] fp16 SW128

    const int pm0 = (wid & 3) * 16;   // proj warp m-tile
    const int pn0 = (wid >> 2) * 32;  // proj warp pix-tile

    for (int pass = 0; pass < 2; pass++) {
        const float* Wm = pass ? W2 : W1;
        const float* xs = pass ? x2 : x1;

        // W -> fp16 [part][m][c64], swizzled
#pragma unroll
        for (int r = 0; r < 32; r++) {
            int idx = t + r * 256;          // 0..8191
            int m = idx >> 7, c = idx & 127;
            __half h = __float2half_rn(__ldg(&Wm[m * CIN + c]));
            *(__half*)(smem + OFF_B0 + (c >> 6) * 8192 +
                       SWZ((uint32_t)(m * 128 + (c & 63) * 2))) = h;
        }
        // x -> fp16 transposed [part][pix][c64], swizzled
        {
            const float* xb = xs + (size_t)b * CIN * HW + hw0;
#pragma unroll
            for (int r = 0; r < 8; r++) {
                int idx = t + r * 256;      // 0..2047 float4
                int c = idx >> 4, q = idx & 15;
                float4 v = *(const float4*)&xb[(size_t)c * HW + q * 4];
                char* xt = smem + OFF_B0 + 16384 + (c >> 6) * 8192;
                int c64 = (c & 63) * 2;
                *(__half*)(xt + SWZ((uint32_t)((q * 4 + 0) * 128 + c64))) = __float2half_rn(v.x);
                *(__half*)(xt + SWZ((uint32_t)((q * 4 + 1) * 128 + c64))) = __float2half_rn(v.y);
                *(__half*)(xt + SWZ((uint32_t)((q * 4 + 2) * 128 + c64))) = __float2half_rn(v.z);
                *(__half*)(xt + SWZ((uint32_t)((q * 4 + 3) * 128 + c64))) = __float2half_rn(v.w);
            }
        }
        __syncthreads();

        // 64x64x128 GEMM: warp tile 16m x 32pix
        float fa[4][4];
#pragma unroll
        for (int nt = 0; nt < 4; nt++)
#pragma unroll
            for (int i = 0; i < 4; i++) fa[nt][i] = 0.0f;

#pragma unroll
        for (int kk = 0; kk < 8; kk++) {
            int part = kk >> 2, kl = kk & 3;
            uint32_t av[4];
            {
                uint32_t aaddr = sW + part * 8192 +
                    SWZ((uint32_t)((pm0 + a_row_l) * 128 + kl * 32 + a_hi16));
                ldsm_x4(av[0], av[1], av[2], av[3], aaddr);
            }
#pragma unroll
            for (int bt = 0; bt < 2; bt++) {
                uint32_t baddr = sX + part * 8192 +
                    SWZ((uint32_t)((pn0 + bt * 16 + b_row_l) * 128 + kl * 32 + b_hi16));
                uint32_t r0, r1, r2, r3;
                ldsm_x4(r0, r1, r2, r3, baddr);
                mma16816(fa[bt * 2],     av, r0, r1);
                mma16816(fa[bt * 2 + 1], av, r2, r3);
            }
        }

        // store fragments
        if (pass == 0) {
#pragma unroll
            for (int nt = 0; nt < 4; nt++) {
                int col = pn0 + nt * 8 + (lid & 3) * 2;
                int rw  = pm0 + (lid >> 2);
                *(uint32_t*)&p1s[rw * P1S + col] =
                    h2_u32(__floats2half2_rn(fa[nt][0], fa[nt][1]));
                *(uint32_t*)&p1s[(rw + 8) * P1S + col] =
                    h2_u32(__floats2half2_rn(fa[nt][2], fa[nt][3]));
            }
        } else {
#pragma unroll
            for (int nt = 0; nt < 4; nt++) {
                int col = pn0 + nt * 8 + (lid & 3) * 2;
                int rw  = pm0 + (lid >> 2);
                *(float2*)&p2s[rw * P2SS + col] = make_float2(fa[nt][0], fa[nt][1]);
                *(float2*)&p2s[(rw + 8) * P2SS + col] = make_float2(fa[nt][2], fa[nt][3]);
            }
        }
        __syncthreads();   // frags stored; safe to reload W/x buffers / read p2s
    }

    // p2 persistent fragment regs (packed half2), from p2s[d][pix]
    uint32_t p2f[32];
#pragma unroll
    for (int mt = 0; mt < 2; mt++)
#pragma unroll
        for (int h = 0; h < 2; h++) {
            int pix = wp * 32 + mt * 16 + h * 8 + g;
#pragma unroll
            for (int kk = 0; kk < 4; kk++)
#pragma unroll
                for (int j = 0; j < 2; j++) {
                    int d = kk * 16 + q2 + j * 8;
                    float lo = p2s[d * P2SS + pix];
                    float hi = p2s[(d + 1) * P2SS + pix];
                    p2f[((mt * 2 + h) * 4 + kk) * 2 + j] =
                        h2_u32(__floats2half2_rn(lo, hi));
                }
        }
    __syncthreads();   // p2s reads done; B0/B2 free for pipeline

    // ===================== mainloop =====================
    const uint32_t offB[3] = {OFF_B1, OFF_B2, OFF_B0};

    float acc[2][8][4];
#pragma unroll
    for (int mt = 0; mt < 2; mt++)
#pragma unroll
        for (int nt = 0; nt < 8; nt++)
#pragma unroll
            for (int i = 0; i < 4; i++) acc[mt][nt][i] = 0.0f;

    // chunk 0 already in flight since kernel start; issue 1 and 2 now.
    if (t == 0) {
        bulk_fetch(sbase + OFF_B2, (const char*)g_Whs + STAGE_BYTES,
                   sbase + OFF_MBAR + 8);
        bulk_fetch(sbase + OFF_B0, (const char*)g_Whs + 2 * (size_t)STAGE_BYTES,
                   sbase + OFF_MBAR + 16);
    }

    for (int ch = 0; ch < 64; ch++) {
        const int s = ch % 3;

        if (t == 0 && ch >= 1 && ch < 62) {
            int s2 = (ch + 2) % 3;
            bulk_fetch(sbase + offB[s2],
                       (const char*)g_Whs + (size_t)(ch + 2) * STAGE_BYTES,
                       sbase + OFF_MBAR + s2 * 8);
        }

        mbar_wait(sbase + OFF_MBAR + s * 8, (ch / 3) & 1);

        uint32_t p1h2[2][2];
#pragma unroll
        for (int mt = 0; mt < 2; mt++)
#pragma unroll
            for (int h = 0; h < 2; h++)
                p1h2[mt][h] = h2_u32(__half2half2(
                    p1s[ch * P1S + wp * 32 + mt * 16 + h * 8 + g]));

        const uint32_t bb = sbase + offB[s];
#pragma unroll
        for (int kk = 0; kk < 4; kk++) {
            uint32_t bfr[4][4];
#pragma unroll
            for (int bp = 0; bp < 4; bp++) {
                int orow = wo * 64 + bp * 16 + b_row_l;
                uint32_t addr = bb + SWZ((uint32_t)(orow * 128 + kk * 32 + b_hi16));
                ldsm_x4(bfr[bp][0], bfr[bp][1], bfr[bp][2], bfr[bp][3], addr);
            }
            uint32_t afr[2][4];
#pragma unroll
            for (int mt = 0; mt < 2; mt++)
#pragma unroll
                for (int rr = 0; rr < 4; rr++) {
                    int h = rr & 1, j = rr >> 1;
                    afr[mt][rr] = h2_u32(__hmul2(
                        u32_h2(p1h2[mt][h]),
                        u32_h2(p2f[((mt * 2 + h) * 4 + kk) * 2 + j])));
                }
#pragma unroll
            for (int bp = 0; bp < 4; bp++) {
                mma16816(acc[0][bp * 2],     afr[0], bfr[bp][0], bfr[bp][1]);
                mma16816(acc[1][bp * 2],     afr[1], bfr[bp][0], bfr[bp][1]);
                mma16816(acc[0][bp * 2 + 1], afr[0], bfr[bp][2], bfr[bp][3]);
                mma16816(acc[1][bp * 2 + 1], afr[1], bfr[bp][2], bfr[bp][3]);
            }
        }

        __syncthreads();   // stage s consumed before tid0 refills it
    }

    // --- epilogue: acc -> smem D, per-pixel LN + GELU + store ---
    float* D = (float*)smem;
#pragma unroll
    for (int mt = 0; mt < 2; mt++) {
#pragma unroll
        for (int nt = 0; nt < 8; nt++) {
            int row = wp * 32 + mt * 16 + (lid >> 2);
            int col = wo * 64 + nt * 8 + (lid & 3) * 2;
            *(float2*)&D[row * DSTRIDE + col] = make_float2(acc[mt][nt][0], acc[mt][nt][1]);
            *(float2*)&D[(row + 8) * DSTRIDE + col] = make_float2(acc[mt][nt][2], acc[mt][nt][3]);
        }
    }
    __syncthreads();

    {
        const int pix = t >> 2;
        const int q   = t & 3;
        const float* Drow = D + pix * DSTRIDE + q * 64;
        float s1 = 0.0f, s2 = 0.0f;
#pragma unroll
        for (int j = 0; j < 32; j++) {
            float2 v = *(const float2*)&Drow[j * 2];
            s1 += v.x + v.y;
            s2 += v.x * v.x + v.y * v.y;
        }
        s1 += __shfl_xor_sync(0xffffffffu, s1, 1);
        s2 += __shfl_xor_sync(0xffffffffu, s2, 1);
        s1 += __shfl_xor_sync(0xffffffffu, s1, 2);
        s2 += __shfl_xor_sync(0xffffffffu, s2, 2);

        float mu = s1 * (1.0f / OUTC);
        float var = s2 * (1.0f / OUTC) - mu * mu;
        float rs = rsqrtf(var + EPS);

        const int P  = pix0 + pix;
        const int bb2 = P / HW;
        const int hw = P - bb2 * HW;
        float* obase = out + (size_t)bb2 * OUTC * HW + hw;
        const float* sg  = (const float*)(smem + OFF_GB);
        const float* sbt = sg + 256;

#pragma unroll
        for (int j = 0; j < 64; j++) {
            int o = q * 64 + j;
            float x = (Drow[j] - mu) * rs * sg[o] + sbt[o];
            float y = 0.5f * x * (1.0f + erff(x * 0.70710678118654752f));
            obase[(size_t)o * HW] = y;
        }
    }
}

// ---------------------------------------------------------------------------
extern "C" void kernel_launch(void* const* d_in, const int* in_sizes, int n_in,
                              void* d_out, int out_size) {
    const float* x1    = (const float*)d_in[0];
    const float* x2    = (const float*)d_in[1];
    const float* W1    = (const float*)d_in[2];
    const float* W2    = (const float*)d_in[3];
    const float* Wp    = (const float*)d_in[4];
    const float* gamma = (const float*)d_in[5];
    const float* beta  = (const float*)d_in[6];
    float* out = (float*)d_out;

    static bool attr_done = false;
    if (!attr_done) {
        cudaFuncSetAttribute(bilinear_mma_kernel,
                             cudaFuncAttributeMaxDynamicSharedMemorySize, SMEM_TOTAL);
        attr_done = true;
    }

    wsplit_kernel<<<(OUTC * KTOT) / 256, 256>>>(Wp);
    bilinear_mma_kernel<<<NPIX / PIXT, 256, SMEM_TOTAL>>>(x1, x2, W1, W2, gamma, beta, out);
}

// round 17
// speedup vs baseline: 1.9156x; 1.0265x over previous
#include <cuda_runtime.h>
#include <cuda_fp16.h>
#include <cstdint>
#include <math.h>

// Problem constants
#define BATCH 8
#define CIN   128
#define HW    3136        // 56*56
#define NPIX  25088       // 8*3136
#define MID   64
#define OUTC  256
#define KTOT  4096        // 64*64
#define EPS   1e-5f
#define PIXT  64          // pixels per CTA tile
#define STAGE_BYTES 32768 // one B chunk stage: 256 o x 64 d fp16, SW128

// Scratch: Wp in fp16, CHUNK-MAJOR PRE-SWIZZLED stage layout.
__device__ __align__(128) __half g_Whs[(size_t)OUTC * KTOT];

// ---------------------------------------------------------------------------
// Helpers (base-arch PTX only: cp.async.bulk / mbarrier / ldmatrix / mma.sync)
// ---------------------------------------------------------------------------
__device__ __forceinline__ uint32_t smem_u32(const void* p) {
    uint32_t a;
    asm("{ .reg .u64 t; cvta.to.shared.u64 t, %1; cvt.u32.u64 %0, t; }" : "=r"(a) : "l"(p));
    return a;
}
__device__ __forceinline__ uint32_t h2_u32(__half2 h) {
    union { __half2 h; uint32_t u; } cv;
    cv.h = h;
    return cv.u;
}
__device__ __forceinline__ __half2 u32_h2(uint32_t u) {
    union { __half2 h; uint32_t u; } cv;
    cv.u = u;
    return cv.h;
}
__device__ __forceinline__ void ldsm_x4(uint32_t& r0, uint32_t& r1, uint32_t& r2, uint32_t& r3,
                                        uint32_t addr) {
    asm volatile("ldmatrix.sync.aligned.m8n8.x4.shared.b16 {%0,%1,%2,%3}, [%4];"
                 : "=r"(r0), "=r"(r1), "=r"(r2), "=r"(r3) : "r"(addr));
}
__device__ __forceinline__ void mma16816(float* c, const uint32_t* a, uint32_t b0, uint32_t b1) {
    asm volatile(
        "mma.sync.aligned.m16n8k16.row.col.f32.f16.f16.f32 "
        "{%0,%1,%2,%3}, {%4,%5,%6,%7}, {%8,%9}, {%0,%1,%2,%3};"
        : "+f"(c[0]), "+f"(c[1]), "+f"(c[2]), "+f"(c[3])
        : "r"(a[0]), "r"(a[1]), "r"(a[2]), "r"(a[3]), "r"(b0), "r"(b1));
}
__device__ __forceinline__ void mbar_init(uint32_t mb, uint32_t cnt) {
    asm volatile("mbarrier.init.shared.b64 [%0], %1;" :: "r"(mb), "r"(cnt) : "memory");
}
__device__ __forceinline__ void bulk_fetch(uint32_t dst, const void* src, uint32_t mb) {
    asm volatile("mbarrier.arrive.expect_tx.shared.b64 _, [%0], %1;"
                 :: "r"(mb), "r"((uint32_t)STAGE_BYTES) : "memory");
    asm volatile("cp.async.bulk.shared::cta.global.mbarrier::complete_tx::bytes "
                 "[%0], [%1], %2, [%3];"
                 :: "r"(dst), "l"(src), "r"((uint32_t)STAGE_BYTES), "r"(mb) : "memory");
}
__device__ __forceinline__ void mbar_wait(uint32_t mb, uint32_t parity) {
    uint32_t done;
    asm volatile(
        "{\n\t.reg .pred p;\n\t"
        "mbarrier.try_wait.parity.shared.b64 p, [%1], %2;\n\t"
        "selp.b32 %0, 1, 0, p;\n\t}"
        : "=r"(done) : "r"(mb), "r"(parity) : "memory");
    while (!done) {
        asm volatile(
            "{\n\t.reg .pred p;\n\t"
            "mbarrier.try_wait.parity.shared.b64 p, [%1], %2;\n\t"
            "selp.b32 %0, 1, 0, p;\n\t}"
            : "=r"(done) : "r"(mb), "r"(parity) : "memory");
    }
}

#define SWZ(off) ((off) ^ (((off) >> 3) & 0x70))

// ---------------------------------------------------------------------------
// SMEM layout (per CTA, bytes). CTA tile: 64 pix x 256 o. 2 CTAs/SM.
// Proj overlays: W1/x1 staging -> B0, W2/x2 staging -> B2, p2s fp32 -> B0
// (after staging reads). B1 prefetches chunk 0 at kernel start.
// Stage rotation: ch%3 -> {B1, B2, B0}.
// ---------------------------------------------------------------------------
#define P1S      66         // p1s stride (halves), padded
#define OFF_P1   0          // p1 tile [m][pix] 64x66 fp16 = 8448
#define OFF_B0   8448       // B stages: 32768 each (SW128, 128B aligned)
#define OFF_B1   41216
#define OFF_B2   73984
#define OFF_GB   106752     // gamma 256 + beta 256 fp32 = 2048
#define OFF_MBAR 108800     // 3 x 8B mbarriers
#define SMEM_TOTAL 108832
#define P2SS     66         // p2s stride (floats)
// Epilogue D tile reuses [0, 66048): 64 rows x 258 fp32 (padded stride)
#define DSTRIDE  258

// ---------------------------------------------------------------------------
// Wp -> fp16 in chunk-major pre-swizzled stage layout.
// ---------------------------------------------------------------------------
__global__ void wsplit_kernel(const float* __restrict__ Wp) {
    int idx = blockIdx.x * 256 + threadIdx.x;   // over OUTC*KTOT
    int o = idx >> 12;          // / KTOT
    int k = idx & (KTOT - 1);
    int ch  = k >> 6;
    int d   = k & 63;
    int seg = d >> 3;
    int w   = d & 7;
    size_t dst = (size_t)ch * STAGE_BYTES + SWZ((uint32_t)(o * 128 + seg * 16)) + w * 2;
    *(__half*)((char*)g_Whs + dst) = __float2half_rn(Wp[idx]);
}

// ---------------------------------------------------------------------------
// Fused: tensor-core projections + fp16 mma.sync GEMM (2-chunk steps) +
// LN + exact GELU. CTA: 64 pix x 256 o. 256 threads = 8 warps.
// ---------------------------------------------------------------------------
__global__ __launch_bounds__(256, 2)
void bilinear_mma_kernel(const float* __restrict__ x1,
                         const float* __restrict__ x2,
                         const float* __restrict__ W1,
                         const float* __restrict__ W2,
                         const float* __restrict__ gamma,
                         const float* __restrict__ beta,
                         float* __restrict__ out) {
    extern __shared__ char smem[];
    const uint32_t sbase = smem_u32(smem);

    const int t   = threadIdx.x;
    const int wid = t >> 5;
    const int lid = t & 31;
    const int wp  = wid >> 2;   // GEMM pixel group (0..1)
    const int wo  = wid & 3;    // GEMM o group (0..3)
    const int g   = lid >> 2;
    const int q2  = (lid & 3) * 2;
    const int pix0 = blockIdx.x * PIXT;
    const int b   = pix0 / HW;
    const int hw0 = pix0 - b * HW;

    const int a_row_l = lid & 15;
    const int a_hi16  = (lid >> 4) * 16;
    const int b_row_l = ((lid >> 4) << 3) + (lid & 7);
    const int b_hi16  = ((lid >> 3) & 1) * 16;

    // mbarriers; tid0 immediately prefetches chunk 0 into B1 (free during proj).
    if (t == 0) {
        mbar_init(sbase + OFF_MBAR, 1);
        mbar_init(sbase + OFF_MBAR + 8, 1);
        mbar_init(sbase + OFF_MBAR + 16, 1);
        bulk_fetch(sbase + OFF_B1, (const char*)g_Whs, sbase + OFF_MBAR);
    }
    {
        float* gb = (float*)(smem + OFF_GB);
        gb[t]       = __ldg(&gamma[t]);
        gb[256 + t] = __ldg(&beta[t]);
    }

    // ===== projection via tensor cores: p = W(64x128) @ x(128x64pix) =======
    __half* p1s = (__half*)(smem + OFF_P1);       // [m][pix] fp16 stride 66
    float*  p2s = (float*)(smem + OFF_B0);        // [d][pix] fp32 stride 66 (post-staging)

    const int pm0 = (wid & 3) * 16;   // proj warp m-tile
    const int pn0 = (wid >> 2) * 32;  // proj warp pix-tile

    // --- stage BOTH passes: W1/x1 -> B0, W2/x2 -> B2 ---
#pragma unroll
    for (int r = 0; r < 32; r++) {
        int idx = t + r * 256;          // 0..8191
        int m = idx >> 7, c = idx & 127;
        uint32_t off = (uint32_t)((c >> 6) * 8192 + SWZ((uint32_t)(m * 128 + (c & 63) * 2)));
        *(__half*)(smem + OFF_B0 + off) = __float2half_rn(__ldg(&W1[m * CIN + c]));
        *(__half*)(smem + OFF_B2 + off) = __float2half_rn(__ldg(&W2[m * CIN + c]));
    }
    {
        const float* xb1 = x1 + (size_t)b * CIN * HW + hw0;
        const float* xb2 = x2 + (size_t)b * CIN * HW + hw0;
#pragma unroll
        for (int r = 0; r < 8; r++) {
            int idx = t + r * 256;      // 0..2047 float4
            int c = idx >> 4, q = idx & 15;
            float4 v1 = *(const float4*)&xb1[(size_t)c * HW + q * 4];
            float4 v2 = *(const float4*)&xb2[(size_t)c * HW + q * 4];
            int c64 = (c & 63) * 2;
            char* xt1 = smem + OFF_B0 + 16384 + (c >> 6) * 8192;
            char* xt2 = smem + OFF_B2 + 16384 + (c >> 6) * 8192;
            *(__half*)(xt1 + SWZ((uint32_t)((q * 4 + 0) * 128 + c64))) = __float2half_rn(v1.x);
            *(__half*)(xt1 + SWZ((uint32_t)((q * 4 + 1) * 128 + c64))) = __float2half_rn(v1.y);
            *(__half*)(xt1 + SWZ((uint32_t)((q * 4 + 2) * 128 + c64))) = __float2half_rn(v1.z);
            *(__half*)(xt1 + SWZ((uint32_t)((q * 4 + 3) * 128 + c64))) = __float2half_rn(v1.w);
            *(__half*)(xt2 + SWZ((uint32_t)((q * 4 + 0) * 128 + c64))) = __float2half_rn(v2.x);
            *(__half*)(xt2 + SWZ((uint32_t)((q * 4 + 1) * 128 + c64))) = __float2half_rn(v2.y);
            *(__half*)(xt2 + SWZ((uint32_t)((q * 4 + 2) * 128 + c64))) = __float2half_rn(v2.z);
            *(__half*)(xt2 + SWZ((uint32_t)((q * 4 + 3) * 128 + c64))) = __float2half_rn(v2.w);
        }
    }
    __syncthreads();

    // --- both proj GEMMs back-to-back (warp tile 16m x 32pix) ---
    float fa1[4][4], fa2[4][4];
#pragma unroll
    for (int nt = 0; nt < 4; nt++)
#pragma unroll
        for (int i = 0; i < 4; i++) { fa1[nt][i] = 0.0f; fa2[nt][i] = 0.0f; }

#pragma unroll
    for (int pass = 0; pass < 2; pass++) {
        const uint32_t sW = sbase + (pass ? OFF_B2 : OFF_B0);
        const uint32_t sX = sW + 16384;
        float (*fa)[4] = pass ? fa2 : fa1;
#pragma unroll
        for (int kk = 0; kk < 8; kk++) {
            int part = kk >> 2, kl = kk & 3;
            uint32_t av[4];
            uint32_t aaddr = sW + part * 8192 +
                SWZ((uint32_t)((pm0 + a_row_l) * 128 + kl * 32 + a_hi16));
            ldsm_x4(av[0], av[1], av[2], av[3], aaddr);
#pragma unroll
            for (int bt = 0; bt < 2; bt++) {
                uint32_t baddr = sX + part * 8192 +
                    SWZ((uint32_t)((pn0 + bt * 16 + b_row_l) * 128 + kl * 32 + b_hi16));
                uint32_t r0, r1, r2, r3;
                ldsm_x4(r0, r1, r2, r3, baddr);
                mma16816(fa[bt * 2],     av, r0, r1);
                mma16816(fa[bt * 2 + 1], av, r2, r3);
            }
        }
    }

    // p1 frags -> p1s (disjoint region, no sync needed yet)
#pragma unroll
    for (int nt = 0; nt < 4; nt++) {
        int col = pn0 + nt * 8 + (lid & 3) * 2;
        int rw  = pm0 + (lid >> 2);
        *(uint32_t*)&p1s[rw * P1S + col] = h2_u32(__floats2half2_rn(fa1[nt][0], fa1[nt][1]));
        *(uint32_t*)&p1s[(rw + 8) * P1S + col] = h2_u32(__floats2half2_rn(fa1[nt][2], fa1[nt][3]));
    }
    __syncthreads();   // all staging reads done; B0 reusable for p2s

    // p2 frags -> p2s fp32 [d][pix] in B0 region
#pragma unroll
    for (int nt = 0; nt < 4; nt++) {
        int col = pn0 + nt * 8 + (lid & 3) * 2;
        int rw  = pm0 + (lid >> 2);
        *(float2*)&p2s[rw * P2SS + col] = make_float2(fa2[nt][0], fa2[nt][1]);
        *(float2*)&p2s[(rw + 8) * P2SS + col] = make_float2(fa2[nt][2], fa2[nt][3]);
    }
    __syncthreads();

    // p2 persistent fragment regs (packed half2), from p2s[d][pix]
    uint32_t p2f[32];
#pragma unroll
    for (int mt = 0; mt < 2; mt++)
#pragma unroll
        for (int h = 0; h < 2; h++) {
            int pix = wp * 32 + mt * 16 + h * 8 + g;
#pragma unroll
            for (int kk = 0; kk < 4; kk++)
#pragma unroll
                for (int j = 0; j < 2; j++) {
                    int d = kk * 16 + q2 + j * 8;
                    float lo = p2s[d * P2SS + pix];
                    float hi = p2s[(d + 1) * P2SS + pix];
                    p2f[((mt * 2 + h) * 4 + kk) * 2 + j] =
                        h2_u32(__floats2half2_rn(lo, hi));
                }
        }
    __syncthreads();   // p2s reads done; B0/B2 free for pipeline

    // ===================== mainloop (2-chunk steps) =====================
    const uint32_t offB[3] = {OFF_B1, OFF_B2, OFF_B0};

    float acc[2][8][4];
#pragma unroll
    for (int mt = 0; mt < 2; mt++)
#pragma unroll
        for (int nt = 0; nt < 8; nt++)
#pragma unroll
            for (int i = 0; i < 4; i++) acc[mt][nt][i] = 0.0f;

    // chunk 0 in flight since kernel start; issue 1 and 2 now.
    if (t == 0) {
        bulk_fetch(sbase + OFF_B2, (const char*)g_Whs + STAGE_BYTES,
                   sbase + OFF_MBAR + 8);
        bulk_fetch(sbase + OFF_B0, (const char*)g_Whs + 2 * (size_t)STAGE_BYTES,
                   sbase + OFF_MBAR + 16);
    }

    auto compute_chunk = [&](int ch, uint32_t bb) {
        uint32_t p1h2[2][2];
#pragma unroll
        for (int mt = 0; mt < 2; mt++)
#pragma unroll
            for (int h = 0; h < 2; h++)
                p1h2[mt][h] = h2_u32(__half2half2(
                    p1s[ch * P1S + wp * 32 + mt * 16 + h * 8 + g]));
#pragma unroll
        for (int kk = 0; kk < 4; kk++) {
            uint32_t bfr[4][4];
#pragma unroll
            for (int bp = 0; bp < 4; bp++) {
                int orow = wo * 64 + bp * 16 + b_row_l;
                uint32_t addr = bb + SWZ((uint32_t)(orow * 128 + kk * 32 + b_hi16));
                ldsm_x4(bfr[bp][0], bfr[bp][1], bfr[bp][2], bfr[bp][3], addr);
            }
            uint32_t afr[2][4];
#pragma unroll
            for (int mt = 0; mt < 2; mt++)
#pragma unroll
                for (int rr = 0; rr < 4; rr++) {
                    int h = rr & 1, j = rr >> 1;
                    afr[mt][rr] = h2_u32(__hmul2(
                        u32_h2(p1h2[mt][h]),
                        u32_h2(p2f[((mt * 2 + h) * 4 + kk) * 2 + j])));
                }
#pragma unroll
            for (int bp = 0; bp < 4; bp++) {
                mma16816(acc[0][bp * 2],     afr[0], bfr[bp][0], bfr[bp][1]);
                mma16816(acc[1][bp * 2],     afr[1], bfr[bp][0], bfr[bp][1]);
                mma16816(acc[0][bp * 2 + 1], afr[0], bfr[bp][2], bfr[bp][3]);
                mma16816(acc[1][bp * 2 + 1], afr[1], bfr[bp][2], bfr[bp][3]);
            }
        }
    };

    for (int ch = 0; ch < 64; ch += 2) {
        const int s0 = ch % 3;
        const int s1 = (ch + 1) % 3;

        mbar_wait(sbase + OFF_MBAR + s0 * 8, (ch / 3) & 1);
        compute_chunk(ch, sbase + offB[s0]);

        mbar_wait(sbase + OFF_MBAR + s1 * 8, ((ch + 1) / 3) & 1);
        compute_chunk(ch + 1, sbase + offB[s1]);

        __syncthreads();   // stages s0, s1 fully consumed by all warps

        if (t == 0 && ch + 3 < 64) {
            bulk_fetch(sbase + offB[s0],
                       (const char*)g_Whs + (size_t)(ch + 3) * STAGE_BYTES,
                       sbase + OFF_MBAR + s0 * 8);
            if (ch + 4 < 64)
                bulk_fetch(sbase + offB[s1],
                           (const char*)g_Whs + (size_t)(ch + 4) * STAGE_BYTES,
                           sbase + OFF_MBAR + s1 * 8);
        }
    }

    // --- epilogue: acc -> smem D, per-pixel LN + GELU + store ---
    float* D = (float*)smem;
#pragma unroll
    for (int mt = 0; mt < 2; mt++) {
#pragma unroll
        for (int nt = 0; nt < 8; nt++) {
            int row = wp * 32 + mt * 16 + (lid >> 2);
            int col = wo * 64 + nt * 8 + (lid & 3) * 2;
            *(float2*)&D[row * DSTRIDE + col] = make_float2(acc[mt][nt][0], acc[mt][nt][1]);
            *(float2*)&D[(row + 8) * DSTRIDE + col] = make_float2(acc[mt][nt][2], acc[mt][nt][3]);
        }
    }
    __syncthreads();

    {
        const int pix = t >> 2;
        const int q   = t & 3;
        const float* Drow = D + pix * DSTRIDE + q * 64;
        float s1 = 0.0f, s2 = 0.0f;
#pragma unroll
        for (int j = 0; j < 32; j++) {
            float2 v = *(const float2*)&Drow[j * 2];
            s1 += v.x + v.y;
            s2 += v.x * v.x + v.y * v.y;
        }
        s1 += __shfl_xor_sync(0xffffffffu, s1, 1);
        s2 += __shfl_xor_sync(0xffffffffu, s2, 1);
        s1 += __shfl_xor_sync(0xffffffffu, s1, 2);
        s2 += __shfl_xor_sync(0xffffffffu, s2, 2);

        float mu = s1 * (1.0f / OUTC);
        float var = s2 * (1.0f / OUTC) - mu * mu;
        float rs = rsqrtf(var + EPS);

        const int P  = pix0 + pix;
        const int bb2 = P / HW;
        const int hw = P - bb2 * HW;
        float* obase = out + (size_t)bb2 * OUTC * HW + hw;
        const float* sg  = (const float*)(smem + OFF_GB);
        const float* sbt = sg + 256;

#pragma unroll
        for (int j = 0; j < 64; j++) {
            int o = q * 64 + j;
            float x = (Drow[j] - mu) * rs * sg[o] + sbt[o];
            float y = 0.5f * x * (1.0f + erff(x * 0.70710678118654752f));
            obase[(size_t)o * HW] = y;
        }
    }
}

// ---------------------------------------------------------------------------
extern "C" void kernel_launch(void* const* d_in, const int* in_sizes, int n_in,
                              void* d_out, int out_size) {
    const float* x1    = (const float*)d_in[0];
    const float* x2    = (const float*)d_in[1];
    const float* W1    = (const float*)d_in[2];
    const float* W2    = (const float*)d_in[3];
    const float* Wp    = (const float*)d_in[4];
    const float* gamma = (const float*)d_in[5];
    const float* beta  = (const float*)d_in[6];
    float* out = (float*)d_out;

    static bool attr_done = false;
    if (!attr_done) {
        cudaFuncSetAttribute(bilinear_mma_kernel,
                             cudaFuncAttributeMaxDynamicSharedMemorySize, SMEM_TOTAL);
        attr_done = true;
    }

    wsplit_kernel<<<(OUTC * KTOT) / 256, 256>>>(Wp);
    bilinear_mma_kernel<<<NPIX / PIXT, 256, SMEM_TOTAL>>>(x1, x2, W1, W2, gamma, beta, out);
}